// round 7
// baseline (speedup 1.0000x reference)
#include <cuda_runtime.h>
#include <cstdint>

#define BS 2
#define NF 16
#define C  32
#define H  128
#define W  128
#define HW (H*W)
#define NM 8
#define NK 3
#define MID (NF/2)

#define PCHUNK 64            // pixels per block
#define PNCH (HW/PCHUNK)     // 256 chunks
#define CG 4                 // channel groups (8 channels = 8 warps each)

typedef unsigned long long ull;

// partials: [b][c][m][ch]  rows of PNCH=256 floats (512 KB total)
__device__ float g_part[BS*C*NM*PNCH];
__device__ float g_pooled[BS*NM*C];
__device__ int   g_ctr;          // zero-init; self-resets each launch

// ---------------------------------------------------------------------------
// Fused masks+pool. grid (PNCH, CG, BS) = 2048 blocks, 256 thr = 8 warps.
//   P1: stage mid-frame chunk (32c x 64px = 8 KB) to smem (L2-hot for cg>0)
//   P2: mask tile (8 x 64) in smem; cg==0 writes it to gmem output
//   P3: pool 16 frames; warp owns channel cg*8+wid; lane owns px pair
//   P4: warp butterfly reduce -> partials
// ---------------------------------------------------------------------------
__global__ void __launch_bounds__(256, 4)
fused_kernel(const float* __restrict__ dec,
             const float* __restrict__ seg_w,
             const float* __restrict__ seg_b,
             float* __restrict__ masks_out)
{
    __shared__ float sdec[C*PCHUNK];    // 8 KB
    __shared__ float smask[NM*PCHUNK];  // 2 KB
    __shared__ float sw[NM*C];          // 1 KB

    const int tid  = threadIdx.x;
    const int ch   = blockIdx.x;
    const int cg   = blockIdx.y;
    const int b    = blockIdx.z;
    const int wid  = tid >> 5;
    const int lane = tid & 31;

    if (tid < NM*C) sw[tid] = seg_w[tid];

    // ---- P1: mid-frame chunk, 512 float4 / 256 thr = 2 each ----
    {
        const float* src = dec + ((size_t)(b*NF + MID))*C*HW + (size_t)ch*PCHUNK;
#pragma unroll
        for (int r = 0; r < 2; r++) {
            int k  = tid + r*256;
            int c  = k >> 4;              // 0..31
            int q4 = k & 15;              // 16 float4 per 64-px row
            reinterpret_cast<float4*>(sdec + c*PCHUNK)[q4] =
                reinterpret_cast<const float4*>(src + (size_t)c*HW)[q4];
        }
    }
    __syncthreads();

    // ---- P2: mask tile, 512 outputs / 256 thr = 2 each ----
#pragma unroll
    for (int r = 0; r < 2; r++) {
        int k  = tid + r*256;
        int m  = k >> 6;                  // 0..7
        int px = k & 63;
        float a = seg_b[m];
#pragma unroll
        for (int c = 0; c < C; c++)
            a += sdec[c*PCHUNK + px] * sw[m*C + c];
        smask[m*PCHUNK + px] = a;
    }
    __syncthreads();

    if (cg == 0) {
        // write mask tile: 256 float2 / 256 thr
        int m  = tid >> 5;
        int pr = tid & 31;
        *reinterpret_cast<float2*>(
            masks_out + ((size_t)b*NM + m)*HW + (size_t)ch*PCHUNK + 2*pr) =
            *reinterpret_cast<const float2*>(smask + m*PCHUNK + 2*pr);
    }

    // ---- P3: pooling ----
    const int c = cg*8 + wid;

    ull mk[NM];
#pragma unroll
    for (int m = 0; m < NM; m++)
        mk[m] = reinterpret_cast<const ull*>(smask + m*PCHUNK)[lane];

    ull acc[NM];
#pragma unroll
    for (int m = 0; m < NM; m++) acc[m] = 0ULL;

    const float* base = dec + ((size_t)b*NF*C + c)*HW + (size_t)ch*PCHUNK;

#pragma unroll 4
    for (int f = 0; f < NF; f++) {
        ull v = reinterpret_cast<const ull*>(base + (size_t)f*C*HW)[lane];
#pragma unroll
        for (int m = 0; m < NM; m++)
            asm("fma.rn.f32x2 %0, %1, %2, %0;" : "+l"(acc[m]) : "l"(v), "l"(mk[m]));
    }

    // ---- P4: reduce ----
#pragma unroll
    for (int m = 0; m < NM; m++) {
        float2 a = *reinterpret_cast<float2*>(&acc[m]);
        float s = a.x + a.y;
#pragma unroll
        for (int off = 16; off; off >>= 1)
            s += __shfl_xor_sync(0xffffffffu, s, off);
        if (lane == 0)
            g_part[(((size_t)b*C + c)*NM + m)*PNCH + ch] = s;
    }
}

// ---------------------------------------------------------------------------
// Reduce + logits: 512 blocks × 256 thr; block reduces one (b,c,m) row of
// 256 floats; LAST block computes the 48 logits.
// ---------------------------------------------------------------------------
__global__ void __launch_bounds__(256)
reduce_logits_kernel(const float* __restrict__ lw,
                     const float* __restrict__ lb,
                     float* __restrict__ out)
{
    const int row = blockIdx.x;            // (b*C + c)*NM + m
    const int tid = threadIdx.x;

    float s = g_part[(size_t)row*PNCH + tid];
#pragma unroll
    for (int off = 16; off; off >>= 1)
        s += __shfl_xor_sync(0xffffffffu, s, off);

    __shared__ float ws[8];
    __shared__ bool  is_last;
    if ((tid & 31) == 0) ws[tid >> 5] = s;
    __syncthreads();

    if (tid == 0) {
        float t = 0.f;
#pragma unroll
        for (int k = 0; k < 8; k++) t += ws[k];
        t *= (1.0f / NF);
        int m = row & (NM-1);
        int c = (row / NM) & (C-1);
        int b = row / (NM*C);
        g_pooled[((size_t)b*NM + m)*C + c] = t;
        __threadfence();
        is_last = (atomicAdd(&g_ctr, 1) == gridDim.x - 1);
    }
    __syncthreads();

    if (is_last) {
        __threadfence();                   // acquire pooled writes
        if (tid < BS*NM*NK) {
            int k  = tid % NK;
            int bm = tid / NK;
            const float* p = g_pooled + (size_t)bm*C;
            float acc = lb[k];
#pragma unroll
            for (int c = 0; c < C; c++) acc += p[c] * lw[k*C + c];
            out[tid] = acc;
        }
        if (tid == 0) g_ctr = 0;           // reset for next graph replay
    }
}

// ---------------------------------------------------------------------------
extern "C" void kernel_launch(void* const* d_in, const int* in_sizes, int n_in,
                              void* d_out, int out_size)
{
    const float* dec   = (const float*)d_in[0];
    const float* seg_w = (const float*)d_in[1];
    const float* seg_b = (const float*)d_in[2];
    const float* lw    = (const float*)d_in[3];
    const float* lb    = (const float*)d_in[4];

    float* out    = (float*)d_out;
    float* logits = out;                 // 48 floats
    float* masks  = out + BS*NM*NK;      // 262144 floats

    fused_kernel        <<<dim3(PNCH, CG, BS), 256>>>(dec, seg_w, seg_b, masks);
    reduce_logits_kernel<<<BS*C*NM, 256>>>(lw, lb, logits);
}